// round 14
// baseline (speedup 1.0000x reference)
#include <cuda_runtime.h>
#include <cuda_fp16.h>
#include <math.h>
#include <stdint.h>

#define Bsz 256
#define Ssz 128
#define Fsz 128
#define Hsz 512
#define G4H 2048
#define Csz 64
#define Lsz 16
#define CPS 10            // k64 chunks per step (K=640)
#define NSTG 4            // pipeline stages

// persistent-kernel smem layout (fp16 2-pass)
#define W_OFF   0                   // resident W (single fp16): 20 x 4KB = 80KB
#define ABASE   81920               // 4 stages x 16KB (each: 2 k32 subs of [Ahi 4K | Alo 4K])
#define MB_OFF  (ABASE + NSTG * 16384)   // full[4] @ +0..31, empty[4] @ +32..63, W @ +64
#define SMEM_PERSIST (MB_OFF + 80)       // 147536

// ---------------- device scratch ----------------
__device__ float g_h[Bsz * Hsz];        // final h (fp32) for mulvdec
__device__ float g_ctx[Bsz * 3 * Hsz];
__device__ float g_t1[Bsz * Hsz];
__device__ unsigned int g_hflag[4][16]; // per (mgroup, k32 h-chunk) warp-arrival counters
// byte-exact smem images for bulk copies
__device__ unsigned char g_wimg[32 * 81920];               // per n-slice: 20 x 4KB fp16 W
__device__ unsigned char g_ximg[128 * 4 * 4 * 8192];       // [t][mgrp][k32-chunk 0-3][hi4K|lo4K]
__device__ unsigned char g_himg[2][4 * 16 * 8192];         // [par][mgrp][k32-chunk 4-19][hi4K|lo4K]

__device__ __forceinline__ float sigmoidf_(float v) {
    return __fdividef(1.0f, 1.0f + __expf(-v));
}
__device__ __forceinline__ float tanhf_(float v) {
    float vc = fminf(fmaxf(v, -15.0f), 15.0f);
    float e = __expf(2.0f * vc);
    return __fdividef(e - 1.0f, e + 1.0f);
}

__device__ __forceinline__ uint32_t smem_to_u32(const void* p) {
    uint32_t a;
    asm("{ .reg .u64 t; cvta.to.shared.u64 t, %1; cvt.u32.u64 %0, t; }" : "=r"(a) : "l"(p));
    return a;
}

#define MBARRIER_INIT(addr, cnt) \
    asm volatile("mbarrier.init.shared.b64 [%0], %1;" :: "r"((uint32_t)(addr)), "r"((uint32_t)(cnt)) : "memory")
#define MBARRIER_ARRIVE(addr) \
    asm volatile("mbarrier.arrive.shared.b64 _, [%0];" :: "r"((uint32_t)(addr)) : "memory")
#define MBARRIER_EXPECT_TX(addr, bytes) \
    asm volatile("mbarrier.arrive.expect_tx.shared.b64 _, [%0], %1;" :: "r"((uint32_t)(addr)), "r"((uint32_t)(bytes)) : "memory")
#define MBARRIER_WAIT_PARITY(mbar_smem_addr, phase_parity) do { \
    uint32_t _mbar = (uint32_t)(mbar_smem_addr); \
    uint32_t _parity = (uint32_t)(phase_parity); \
    uint32_t _done; \
    asm volatile("{\n\t.reg .pred p;\n\t" \
        "mbarrier.try_wait.parity.acquire.cta.shared::cta.b64 p, [%1], %2;\n\t" \
        "selp.b32 %0, 1, 0, p;\n\t}" \
        : "=r"(_done) : "r"(_mbar), "r"(_parity) : "memory"); \
    if (!_done) { \
        asm volatile("{\n\t.reg .pred P1;\n\t" \
            "WAIT_LOOP_%=:\n\t" \
            "mbarrier.try_wait.parity.acquire.cta.shared::cta.b64 P1, [%0], %1, 0x989680;\n\t" \
            "@P1 bra.uni WAIT_DONE_%=;\n\t" \
            "bra.uni WAIT_LOOP_%=;\n\t" \
            "WAIT_DONE_%=:\n\t}" \
            :: "r"(_mbar), "r"(_parity) : "memory"); \
    } \
} while (0)
#define FENCE_ASYNC_SHARED() asm volatile("fence.proxy.async.shared::cta;" ::: "memory")

__device__ __forceinline__ void bulk_g2s(uint32_t dst, const void* src, uint32_t bytes, uint32_t mbar) {
    asm volatile("cp.async.bulk.shared::cluster.global.mbarrier::complete_tx::bytes [%0], [%1], %2, [%3];"
                 :: "r"(dst), "l"(src), "r"(bytes), "r"(mbar) : "memory");
}

#define LDSM4(r0, r1, r2, r3, a) \
    asm volatile("ldmatrix.sync.aligned.m8n8.x4.shared.b16 {%0,%1,%2,%3}, [%4];" \
                 : "=r"(r0), "=r"(r1), "=r"(r2), "=r"(r3) : "r"(a))

// fp16 HMMA, fp32 accumulate
#define MMAH(c, a0, a1, a2, a3, b0, b1) \
    asm volatile("mma.sync.aligned.m16n8k16.row.col.f32.f16.f16.f32 " \
                 "{%0,%1,%2,%3}, {%4,%5,%6,%7}, {%8,%9}, {%0,%1,%2,%3};" \
                 : "+f"((c)[0]), "+f"((c)[1]), "+f"((c)[2]), "+f"((c)[3]) \
                 : "r"(a0), "r"(a1), "r"(a2), "r"(a3), "r"(b0), "r"(b1))

// fp16 hi/lo split: v = hi + lo
__device__ __forceinline__ void hsplit(float v, unsigned short& h, unsigned short& l) {
    __half hh = __float2half(v);
    float r = v - __half2float(hh);
    __half hl = __float2half(r);
    h = *(unsigned short*)&hh;
    l = *(unsigned short*)&hl;
}

// ---------------- unified prep kernel ----------------
__global__ __launch_bounds__(256) void prep_kernel(
    const float* __restrict__ x, const float* __restrict__ context,
    const float* __restrict__ cg_w1, const float* __restrict__ cg_b1,
    const float* __restrict__ W_ih, const float* __restrict__ W_hh)
{
    const int bid = blockIdx.x;
    const int tid = threadIdx.x;

    if (bid < 512) {
        if (tid < 128)
            ((unsigned long long*)g_himg[0])[(size_t)bid * 128 + tid] = 0ull;
        if (bid == 0 && tid >= 128 && tid < 192)
            ((unsigned int*)g_hflag)[tid - 128] = 0u;

        const int t = bid >> 2, mg = bid & 3;
        const int cr = tid >> 2, s4 = tid & 3;
        const int b = mg * 64 + cr;
        const uint32_t seg = (s4 >> 1) * 2048 + cr * 32 + (((s4) ^ (cr >> 2)) & 1) * 16;
        unsigned char* base = g_ximg + (size_t)(t * 4 + mg) * 4 * 8192;
#pragma unroll
        for (int c = 0; c < 4; c++) {
            const float* src = x + (size_t)b * (Ssz * Fsz) + (size_t)t * Fsz + c * 32 + s4 * 8;
            float4 v0 = *(const float4*)src;
            float4 v1 = *(const float4*)(src + 4);
            unsigned short h[8], l[8];
            hsplit(v0.x, h[0], l[0]); hsplit(v0.y, h[1], l[1]);
            hsplit(v0.z, h[2], l[2]); hsplit(v0.w, h[3], l[3]);
            hsplit(v1.x, h[4], l[4]); hsplit(v1.y, h[5], l[5]);
            hsplit(v1.z, h[6], l[6]); hsplit(v1.w, h[7], l[7]);
            uint4 hp, lp;
            hp.x = (uint32_t)h[0] | ((uint32_t)h[1] << 16);
            hp.y = (uint32_t)h[2] | ((uint32_t)h[3] << 16);
            hp.z = (uint32_t)h[4] | ((uint32_t)h[5] << 16);
            hp.w = (uint32_t)h[6] | ((uint32_t)h[7] << 16);
            lp.x = (uint32_t)l[0] | ((uint32_t)l[1] << 16);
            lp.y = (uint32_t)l[2] | ((uint32_t)l[3] << 16);
            lp.z = (uint32_t)l[4] | ((uint32_t)l[5] << 16);
            lp.w = (uint32_t)l[6] | ((uint32_t)l[7] << 16);
            *(uint4*)(base + c * 8192 + seg)        = hp;
            *(uint4*)(base + c * 8192 + 4096 + seg) = lp;
        }
        return;
    }

    if (bid < 1152) {
        const int w = bid - 512;
        const int ns = w & 31, c = w >> 5;
        const int jl = tid & 15;
        const int g = (tid >> 4) & 3;
        const int kseg = tid >> 6;
        const int r = jl * 4 + g;
        const int col = g * Hsz + ns * 16 + jl;
        const int k0 = c * 32 + kseg * 8;
        unsigned short h[8];
#pragma unroll
        for (int e = 0; e < 8; e++) {
            const int k = k0 + e;
            float wv = (k < Fsz) ? W_ih[k * G4H + col] : W_hh[(k - Fsz) * G4H + col];
            __half hh = __float2half(wv);
            h[e] = *(unsigned short*)&hh;
        }
        uint4 hp;
        hp.x = (uint32_t)h[0] | ((uint32_t)h[1] << 16);
        hp.y = (uint32_t)h[2] | ((uint32_t)h[3] << 16);
        hp.z = (uint32_t)h[4] | ((uint32_t)h[5] << 16);
        hp.w = (uint32_t)h[6] | ((uint32_t)h[7] << 16);
        const uint32_t seg = (kseg >> 1) * 2048 + r * 32 + (((kseg ^ (r >> 2)) & 1) << 4);
        *(uint4*)(g_wimg + (size_t)ns * 81920 + (size_t)c * 4096 + seg) = hp;
        return;
    }

    // ---- ctx layer 1 ----
    {
        const int q = bid - 1152;
        const int n0 = (q & 7) * 64;
        const int m0 = (q >> 3) * 64;
        const int tc = tid & 15;
        const int rg = tid >> 4;

        __shared__ float As[16][68];
        __shared__ float Ws[16][68];

        float4 acc[4];
#pragma unroll
        for (int i = 0; i < 4; i++) acc[i] = make_float4(0.f, 0.f, 0.f, 0.f);

        for (int k0 = 0; k0 < 64; k0 += 16) {
#pragma unroll
            for (int u = 0; u < 4; u++) {
                int i = tid + u * 256;
                int r = i >> 4, kk = i & 15;
                As[kk][r] = context[(m0 + r) * 64 + k0 + kk];
                int kr = i >> 6, cc = i & 63;
                Ws[kr][cc] = cg_w1[(k0 + kr) * 512 + n0 + cc];
            }
            __syncthreads();
#pragma unroll
            for (int kk = 0; kk < 16; kk++) {
                float4 w = *(const float4*)&Ws[kk][tc * 4];
                float4 a = *(const float4*)&As[kk][rg * 4];
                acc[0].x += a.x * w.x; acc[0].y += a.x * w.y; acc[0].z += a.x * w.z; acc[0].w += a.x * w.w;
                acc[1].x += a.y * w.x; acc[1].y += a.y * w.y; acc[1].z += a.y * w.z; acc[1].w += a.y * w.w;
                acc[2].x += a.z * w.x; acc[2].y += a.z * w.y; acc[2].z += a.z * w.z; acc[2].w += a.z * w.w;
                acc[3].x += a.w * w.x; acc[3].y += a.w * w.y; acc[3].z += a.w * w.z; acc[3].w += a.w * w.w;
            }
            __syncthreads();
        }

        int col = n0 + tc * 4;
        float4 bv = *(const float4*)&cg_b1[col];
#pragma unroll
        for (int ri = 0; ri < 4; ri++) {
            int row = m0 + rg * 4 + ri;
            float4 v = acc[ri];
            v.x = fmaxf(v.x + bv.x, 0.f); v.y = fmaxf(v.y + bv.y, 0.f);
            v.z = fmaxf(v.z + bv.z, 0.f); v.w = fmaxf(v.w + bv.w, 0.f);
            *(float4*)&g_t1[row * 512 + col] = v;
        }
    }
}

// ---------------- ctx layer 2 ----------------
__global__ __launch_bounds__(256) void ctx2_kernel(
    const float* __restrict__ W, const float* __restrict__ bias)
{
    const int n0 = blockIdx.x * 64;
    const int m0 = blockIdx.y * 64;
    const int tid = threadIdx.x;
    const int tc = tid & 15;
    const int rg = tid >> 4;

    __shared__ float As[16][68];
    __shared__ float Ws[16][68];

    float4 acc[4];
#pragma unroll
    for (int i = 0; i < 4; i++) acc[i] = make_float4(0.f, 0.f, 0.f, 0.f);

    for (int k0 = 0; k0 < 512; k0 += 16) {
#pragma unroll
        for (int u = 0; u < 4; u++) {
            int i = tid + u * 256;
            int r = i >> 4, kk = i & 15;
            As[kk][r] = g_t1[(m0 + r) * 512 + k0 + kk];
            int kr = i >> 6, c = i & 63;
            Ws[kr][c] = W[(k0 + kr) * 1536 + n0 + c];
        }
        __syncthreads();
#pragma unroll
        for (int kk = 0; kk < 16; kk++) {
            float4 w = *(const float4*)&Ws[kk][tc * 4];
            float4 a = *(const float4*)&As[kk][rg * 4];
            acc[0].x += a.x * w.x; acc[0].y += a.x * w.y; acc[0].z += a.x * w.z; acc[0].w += a.x * w.w;
            acc[1].x += a.y * w.x; acc[1].y += a.y * w.y; acc[1].z += a.y * w.z; acc[1].w += a.y * w.w;
            acc[2].x += a.z * w.x; acc[2].y += a.z * w.y; acc[2].z += a.z * w.z; acc[2].w += a.z * w.w;
            acc[3].x += a.w * w.x; acc[3].y += a.w * w.y; acc[3].z += a.w * w.z; acc[3].w += a.w * w.w;
        }
        __syncthreads();
    }

    int col = n0 + tc * 4;
    float4 bv = *(const float4*)&bias[col];
#pragma unroll
    for (int ri = 0; ri < 4; ri++) {
        int row = m0 + rg * 4 + ri;
        float4 v = acc[ri];
        v.x = sigmoidf_(v.x + bv.x); v.y = sigmoidf_(v.y + bv.y);
        v.z = sigmoidf_(v.z + bv.z); v.w = sigmoidf_(v.w + bv.w);
        *(float4*)&g_ctx[row * 1536 + col] = v;
    }
}

// ---------------- persistent LSTM: fp16 2-pass, 4-lane parallel producer ----------------
__global__ __launch_bounds__(288, 1) void lstm_persist(
    const float* __restrict__ b_ih, const float* __restrict__ b_hh)
{
    extern __shared__ char smbuf[];
    const uint32_t sb = smem_to_u32(smbuf);
    const int tid = threadIdx.x;
    const int lane = tid & 31, wid = tid >> 5;
    const int bx = blockIdx.x;
    const int nsl = bx & 31;
    const int j0 = nsl * 16;
    const int mg = bx >> 5;
    const int m0 = mg * 64;

    const uint32_t mbF = sb + MB_OFF;
    const uint32_t mbE = sb + MB_OFF + 32;
    const uint32_t mbW = sb + MB_OFF + 64;

    if (tid == 0) {
#pragma unroll
        for (int s = 0; s < NSTG; s++) {
            MBARRIER_INIT(mbF + s * 8, 1);
            MBARRIER_INIT(mbE + s * 8, 8);
        }
        MBARRIER_INIT(mbW, 1);
    }
    FENCE_ASYNC_SHARED();
    __syncthreads();

    // ---- resident W slice (80KB fp16) ----
    if (tid == 0) {
        MBARRIER_EXPECT_TX(mbW, 81920u);
        const unsigned char* src = g_wimg + (size_t)nsl * 81920;
#pragma unroll
        for (int i = 0; i < 5; i++)
            bulk_g2s(sb + W_OFF + i * 16384, src + i * 16384, 16384u, mbW);
    }
    MBARRIER_WAIT_PARITY(mbW, 0);
    __syncthreads();

    if (wid == 8) {
        // ======== producer: 4 lanes, each owns one pipeline stage ========
        if (lane < 4) {
            const int s = lane;
            unsigned ph = 1u;        // empty barrier: first wait passes immediately
#pragma unroll 1
            for (int gc = s; gc < Ssz * CPS; gc += 4) {
                MBARRIER_WAIT_PARITY(mbE + s * 8, ph);
                ph ^= 1u;
                const int tp = gc / CPS, cc = gc % CPS;
                const unsigned char* src;
                if (cc < 2) {
                    src = g_ximg + ((size_t)(tp * 4 + mg) * 4 + 2 * cc) * 8192;
                } else {
                    if (tp > 0) {
                        const unsigned tgt = 16u * (unsigned)tp;
                        const int hc = 2 * cc - 4;
#pragma unroll
                        for (int q = 0; q < 2; q++) {
                            unsigned v;
                            do {
                                asm volatile("ld.global.acquire.gpu.u32 %0, [%1];"
                                             : "=r"(v) : "l"(&g_hflag[mg][hc + q]));
                                if (v >= tgt) break;
                                __nanosleep(32);
                            } while (true);
                        }
                    }
                    src = g_himg[tp & 1] + (size_t)(mg * 16 + (2 * cc - 4)) * 8192;
                }
                MBARRIER_EXPECT_TX(mbF + s * 8, 16384u);
                bulk_g2s(sb + ABASE + s * 16384,        src,        8192u, mbF + s * 8);
                bulk_g2s(sb + ABASE + s * 16384 + 8192, src + 8192, 8192u, mbF + s * 8);
            }
        }
        return;
    }

    // ================= consumers (warps 0-7) =================
    const int m0w = (wid >> 1) * 16;
    const int n0w = (wid & 1) * 32;
    const int rA = m0w + (lane & 15);
    const uint32_t offA = rA * 32 + ((((lane >> 4) ^ (rA >> 2)) & 1) << 4);
    const int rB = n0w + ((lane >> 4) << 3) + (lane & 7);
    const uint32_t offB = rB * 32 + ((((lane >> 3) ^ (rB >> 2)) & 1) << 4);

    const int rowc = m0w + (lane >> 2) + (lane & 1) * 8;
    const int bglob = m0 + rowc;
    int jc[4];
    float bi[4], bf4[4], bg4[4], bo4[4];
    float creg[4], cti[4], ctf[4], cto[4];
    uint32_t hoff[4];
#pragma unroll
    for (int nt = 0; nt < 4; nt++) {
        const int j = j0 + (n0w >> 2) + nt * 2 + ((lane >> 1) & 1);
        jc[nt] = j;
        bi[nt]  = b_ih[j]        + b_hh[j];
        bf4[nt] = b_ih[j + 512]  + b_hh[j + 512];
        bg4[nt] = b_ih[j + 1024] + b_hh[j + 1024];
        bo4[nt] = b_ih[j + 1536] + b_hh[j + 1536];
        cti[nt] = g_ctx[(size_t)bglob * (3 * Hsz) + j];
        ctf[nt] = g_ctx[(size_t)bglob * (3 * Hsz) + j + 512];
        cto[nt] = g_ctx[(size_t)bglob * (3 * Hsz) + j + 1024];
        creg[nt] = 0.f;
        const int hc = j >> 5, kj = j & 31, s4h = kj >> 3, eh = kj & 7;
        hoff[nt] = (uint32_t)(mg * 16 + hc) * 8192 + (s4h >> 1) * 2048 + (eh << 1)
                 + (uint32_t)rowc * 32
                 + ((((unsigned)s4h ^ ((unsigned)rowc >> 2)) & 1u) << 4);
    }

    unsigned fph = 0;

#pragma unroll 1
    for (int t = 0; t < Ssz; t++) {
        float acc[4][4];
#pragma unroll
        for (int i = 0; i < 4; i++)
#pragma unroll
            for (int q = 0; q < 4; q++) acc[i][q] = 0.f;

#pragma unroll 1
        for (int c = 0; c < CPS; c++) {
            const int gc = t * CPS + c;
            const int s = gc & 3;
            MBARRIER_WAIT_PARITY(mbF + s * 8, (fph >> s) & 1u);
            fph ^= (1u << s);

            const uint32_t st = sb + ABASE + s * 16384;
#pragma unroll
            for (int sub = 0; sub < 2; sub++) {
                const int oc = 2 * c + sub;
                const uint32_t ast = st + sub * 8192;
                const uint32_t wst = sb + W_OFF + oc * 4096;
#pragma unroll
                for (int kb = 0; kb < 2; kb++) {
                    uint32_t a0, a1, a2, a3, l0, l1, l2, l3;
                    LDSM4(a0, a1, a2, a3, ast + kb * 2048 + offA);
                    LDSM4(l0, l1, l2, l3, ast + 4096 + kb * 2048 + offA);
                    uint32_t b0, b1, b2, b3, b4, b5, b6, b7;
                    LDSM4(b0, b1, b2, b3, wst + kb * 2048 + offB);
                    LDSM4(b4, b5, b6, b7, wst + kb * 2048 + offB + 512);

                    MMAH(acc[0], a0, a1, a2, a3, b0, b1);
                    MMAH(acc[1], a0, a1, a2, a3, b2, b3);
                    MMAH(acc[2], a0, a1, a2, a3, b4, b5);
                    MMAH(acc[3], a0, a1, a2, a3, b6, b7);
                    MMAH(acc[0], l0, l1, l2, l3, b0, b1);
                    MMAH(acc[1], l0, l1, l2, l3, b2, b3);
                    MMAH(acc[2], l0, l1, l2, l3, b4, b5);
                    MMAH(acc[3], l0, l1, l2, l3, b6, b7);
                }
            }
            if (lane == 0) MBARRIER_ARRIVE(mbE + s * 8);
        }

        // ---- shuffle epilogue ----
        unsigned char* himg = g_himg[(t + 1) & 1];
        const bool oddq = (lane & 1);
#pragma unroll
        for (int nt = 0; nt < 4; nt++) {
            float x0 = __shfl_xor_sync(0xffffffffu, acc[nt][0], 1);
            float x1 = __shfl_xor_sync(0xffffffffu, acc[nt][1], 1);
            float x2 = __shfl_xor_sync(0xffffffffu, acc[nt][2], 1);
            float x3 = __shfl_xor_sync(0xffffffffu, acc[nt][3], 1);
            float g0, g1, g2, g3;
            if (!oddq) { g0 = acc[nt][0]; g1 = acc[nt][1]; g2 = x0; g3 = x1; }
            else       { g0 = x2; g1 = x3; g2 = acc[nt][2]; g3 = acc[nt][3]; }
            float iv = sigmoidf_(g0 + bi[nt])  * cti[nt];
            float fv = sigmoidf_(g1 + bf4[nt]) * ctf[nt];
            float gg = tanhf_(g2 + bg4[nt]);
            float ov = sigmoidf_(g3 + bo4[nt]) * cto[nt];
            float cn = fv * creg[nt] + iv * gg;
            creg[nt] = cn;
            float hn = ov * tanhf_(cn);
            __half hb = __float2half(hn);
            *(__half*)(himg + hoff[nt])        = hb;
            *(__half*)(himg + hoff[nt] + 4096) = __float2half(hn - __half2float(hb));
            if (t == Ssz - 1) g_h[bglob * Hsz + jc[nt]] = hn;
        }

        __syncwarp();
        if (lane == 0) {
            __threadfence();
            atomicAdd(&g_hflag[mg][nsl >> 1], 1u);
        }
    }
}

// ---------------- fused mu / log_var / z / decoder: 2 batch rows per block ----------------
__global__ __launch_bounds__(512) void mulvdec_kernel(
    const float* __restrict__ mu_w, const float* __restrict__ mu_b,
    const float* __restrict__ lv_w, const float* __restrict__ lv_b,
    const float* __restrict__ eps,
    const float* __restrict__ dec_w1, const float* __restrict__ dec_b1,
    const float* __restrict__ dec_w2, const float* __restrict__ dec_b2,
    float* __restrict__ out)
{
    const int b0 = blockIdx.x * 2;
    const int tid = threadIdx.x;
    __shared__ float sh[2][512];
    __shared__ float smu[2][16], slv[2][16];
    __shared__ float sz[2][16];
    __shared__ float st[2][512];
    __shared__ float part[2][4][128];

    sh[0][tid] = g_h[(size_t)b0 * Hsz + tid];
    sh[1][tid] = g_h[(size_t)(b0 + 1) * Hsz + tid];
    __syncthreads();

    const int w = tid >> 5, lane = tid & 31;
    const int l = w;   // 16 warps -> 16 latent dims
    float sm0 = 0.f, sl0 = 0.f, sm1 = 0.f, sl1 = 0.f;
    for (int k = lane; k < Hsz; k += 32) {
        float wm = mu_w[k * Lsz + l];
        float wl = lv_w[k * Lsz + l];
        float h0 = sh[0][k], h1 = sh[1][k];
        sm0 += h0 * wm; sl0 += h0 * wl;
        sm1 += h1 * wm; sl1 += h1 * wl;
    }
#pragma unroll
    for (int o = 16; o > 0; o >>= 1) {
        sm0 += __shfl_down_sync(0xffffffffu, sm0, o);
        sl0 += __shfl_down_sync(0xffffffffu, sl0, o);
        sm1 += __shfl_down_sync(0xffffffffu, sm1, o);
        sl1 += __shfl_down_sync(0xffffffffu, sl1, o);
    }
    if (lane == 0) {
        smu[0][l] = sm0; slv[0][l] = sl0;
        smu[1][l] = sm1; slv[1][l] = sl1;
    }
    __syncthreads();

    if (tid < 32) {
        const int r = tid >> 4, li = tid & 15;
        float mu = smu[r][li] + mu_b[li];
        float lv = slv[r][li] + lv_b[li];
        out[Bsz * Fsz + (b0 + r) * Lsz + li] = mu;
        out[Bsz * Fsz + Bsz * Lsz + (b0 + r) * Lsz + li] = lv;
        sz[r][li] = mu + eps[(b0 + r) * Lsz + li] * expf(0.5f * lv);
    }
    __syncthreads();

    // decoder layer 1 (weight loaded once, applied to both rows)
    {
        float s0 = dec_b1[tid], s1 = s0;
#pragma unroll
        for (int k = 0; k < 16; k++) {
            float wv = dec_w1[k * Hsz + tid];
            s0 += sz[0][k] * wv;
            s1 += sz[1][k] * wv;
        }
        st[0][tid] = fmaxf(s0, 0.f);
        st[1][tid] = fmaxf(s1, 0.f);
    }
    __syncthreads();

    // decoder layer 2 (weight loaded once, 2 accs per row)
    {
        const int col = tid & 127, qr = tid >> 7;
        const int kb = qr * 128;
        float a0 = 0.f, a1 = 0.f, c0 = 0.f, c1 = 0.f;
#pragma unroll 4
        for (int k = 0; k < 128; k += 2) {
            float w0 = dec_w2[(kb + k) * Fsz + col];
            float w1 = dec_w2[(kb + k + 1) * Fsz + col];
            a0 += st[0][kb + k] * w0;  a1 += st[0][kb + k + 1] * w1;
            c0 += st[1][kb + k] * w0;  c1 += st[1][kb + k + 1] * w1;
        }
        part[0][qr][col] = a0 + a1;
        part[1][qr][col] = c0 + c1;
        __syncthreads();
        if (tid < 256) {
            const int r = tid >> 7, c = tid & 127;
            out[(b0 + r) * Fsz + c] = dec_b2[c] +
                part[r][0][c] + part[r][1][c] + part[r][2][c] + part[r][3][c];
        }
    }
}

// ---------------- launch ----------------
extern "C" void kernel_launch(void* const* d_in, const int* in_sizes, int n_in,
                              void* d_out, int out_size)
{
    const float* x       = (const float*)d_in[0];
    const float* context = (const float*)d_in[1];
    const float* eps     = (const float*)d_in[2];
    const float* W_ih    = (const float*)d_in[3];
    const float* b_ih    = (const float*)d_in[4];
    const float* W_hh    = (const float*)d_in[5];
    const float* b_hh    = (const float*)d_in[6];
    const float* cg_w1   = (const float*)d_in[7];
    const float* cg_b1   = (const float*)d_in[8];
    const float* cg_w2   = (const float*)d_in[9];
    const float* cg_b2   = (const float*)d_in[10];
    const float* mu_w    = (const float*)d_in[11];
    const float* mu_b    = (const float*)d_in[12];
    const float* lv_w    = (const float*)d_in[13];
    const float* lv_b    = (const float*)d_in[14];
    const float* dec_w1  = (const float*)d_in[15];
    const float* dec_b1  = (const float*)d_in[16];
    const float* dec_w2  = (const float*)d_in[17];
    const float* dec_b2  = (const float*)d_in[18];
    float* out = (float*)d_out;

    static int smem_set = 0;
    if (!smem_set) {
        cudaFuncSetAttribute(lstm_persist, cudaFuncAttributeMaxDynamicSharedMemorySize,
                             SMEM_PERSIST);
        smem_set = 1;
    }

    prep_kernel<<<1184, 256>>>(x, context, cg_w1, cg_b1, W_ih, W_hh);
    ctx2_kernel<<<dim3(24, 4), 256>>>(cg_w2, cg_b2);

    lstm_persist<<<128, 288, SMEM_PERSIST>>>(b_ih, b_hh);

    mulvdec_kernel<<<Bsz / 2, 512>>>(mu_w, mu_b, lv_w, lv_b, eps,
                                     dec_w1, dec_b1, dec_w2, dec_b2, out);
}

// round 15
// speedup vs baseline: 1.3506x; 1.3506x over previous
#include <cuda_runtime.h>
#include <cuda_fp16.h>
#include <math.h>
#include <stdint.h>

#define Bsz 256
#define Ssz 128
#define Fsz 128
#define Hsz 512
#define G4H 2048
#define Csz 64
#define Lsz 16
#define CPS 10            // k64 chunks per step (K=640)
#define NSTG 4            // pipeline stages

// persistent-kernel smem layout (fp16 2-pass)
#define W_OFF   0                   // resident W (single fp16): 20 x 4KB = 80KB
#define ABASE   81920               // 4 stages x 16KB (each: 2 k32 subs of [Ahi 4K | Alo 4K])
#define MB_OFF  (ABASE + NSTG * 16384)   // full[4] @ +0..31, empty[4] @ +32..63, W @ +64
#define SMEM_PERSIST (MB_OFF + 80)       // 147536

// ---------------- device scratch ----------------
__device__ float g_h[Bsz * Hsz];        // final h (fp32) for mulvdec
__device__ float g_ctx[Bsz * 3 * Hsz];
__device__ float g_t1[Bsz * Hsz];
__device__ unsigned int g_hflag[4][16]; // per (mgroup, k32 h-chunk) warp-arrival counters
// byte-exact smem images for bulk copies
__device__ unsigned char g_wimg[32 * 81920];               // per n-slice: 20 x 4KB fp16 W
__device__ unsigned char g_ximg[128 * 4 * 4 * 8192];       // [t][mgrp][k32-chunk 0-3][hi4K|lo4K]
__device__ unsigned char g_himg[2][4 * 16 * 8192];         // [par][mgrp][k32-chunk 4-19][hi4K|lo4K]

__device__ __forceinline__ float sigmoidf_(float v) {
    return __fdividef(1.0f, 1.0f + __expf(-v));
}
__device__ __forceinline__ float tanhf_(float v) {
    float vc = fminf(fmaxf(v, -15.0f), 15.0f);
    float e = __expf(2.0f * vc);
    return __fdividef(e - 1.0f, e + 1.0f);
}

__device__ __forceinline__ uint32_t smem_to_u32(const void* p) {
    uint32_t a;
    asm("{ .reg .u64 t; cvta.to.shared.u64 t, %1; cvt.u32.u64 %0, t; }" : "=r"(a) : "l"(p));
    return a;
}

#define MBARRIER_INIT(addr, cnt) \
    asm volatile("mbarrier.init.shared.b64 [%0], %1;" :: "r"((uint32_t)(addr)), "r"((uint32_t)(cnt)) : "memory")
#define MBARRIER_ARRIVE(addr) \
    asm volatile("mbarrier.arrive.shared.b64 _, [%0];" :: "r"((uint32_t)(addr)) : "memory")
#define MBARRIER_EXPECT_TX(addr, bytes) \
    asm volatile("mbarrier.arrive.expect_tx.shared.b64 _, [%0], %1;" :: "r"((uint32_t)(addr)), "r"((uint32_t)(bytes)) : "memory")
#define MBARRIER_WAIT_PARITY(mbar_smem_addr, phase_parity) do { \
    uint32_t _mbar = (uint32_t)(mbar_smem_addr); \
    uint32_t _parity = (uint32_t)(phase_parity); \
    uint32_t _done; \
    asm volatile("{\n\t.reg .pred p;\n\t" \
        "mbarrier.try_wait.parity.acquire.cta.shared::cta.b64 p, [%1], %2;\n\t" \
        "selp.b32 %0, 1, 0, p;\n\t}" \
        : "=r"(_done) : "r"(_mbar), "r"(_parity) : "memory"); \
    if (!_done) { \
        asm volatile("{\n\t.reg .pred P1;\n\t" \
            "WAIT_LOOP_%=:\n\t" \
            "mbarrier.try_wait.parity.acquire.cta.shared::cta.b64 P1, [%0], %1, 0x989680;\n\t" \
            "@P1 bra.uni WAIT_DONE_%=;\n\t" \
            "bra.uni WAIT_LOOP_%=;\n\t" \
            "WAIT_DONE_%=:\n\t}" \
            :: "r"(_mbar), "r"(_parity) : "memory"); \
    } \
} while (0)
#define FENCE_ASYNC_SHARED() asm volatile("fence.proxy.async.shared::cta;" ::: "memory")

__device__ __forceinline__ void bulk_g2s(uint32_t dst, const void* src, uint32_t bytes, uint32_t mbar) {
    asm volatile("cp.async.bulk.shared::cluster.global.mbarrier::complete_tx::bytes [%0], [%1], %2, [%3];"
                 :: "r"(dst), "l"(src), "r"(bytes), "r"(mbar) : "memory");
}

#define LDSM4(r0, r1, r2, r3, a) \
    asm volatile("ldmatrix.sync.aligned.m8n8.x4.shared.b16 {%0,%1,%2,%3}, [%4];" \
                 : "=r"(r0), "=r"(r1), "=r"(r2), "=r"(r3) : "r"(a))

// fp16 HMMA, fp32 accumulate
#define MMAH(c, a0, a1, a2, a3, b0, b1) \
    asm volatile("mma.sync.aligned.m16n8k16.row.col.f32.f16.f16.f32 " \
                 "{%0,%1,%2,%3}, {%4,%5,%6,%7}, {%8,%9}, {%0,%1,%2,%3};" \
                 : "+f"((c)[0]), "+f"((c)[1]), "+f"((c)[2]), "+f"((c)[3]) \
                 : "r"(a0), "r"(a1), "r"(a2), "r"(a3), "r"(b0), "r"(b1))

// fp16 hi/lo split: v = hi + lo
__device__ __forceinline__ void hsplit(float v, unsigned short& h, unsigned short& l) {
    __half hh = __float2half(v);
    float r = v - __half2float(hh);
    __half hl = __float2half(r);
    h = *(unsigned short*)&hh;
    l = *(unsigned short*)&hl;
}

// ---------------- unified prep kernel ----------------
__global__ __launch_bounds__(256) void prep_kernel(
    const float* __restrict__ x, const float* __restrict__ context,
    const float* __restrict__ cg_w1, const float* __restrict__ cg_b1,
    const float* __restrict__ W_ih, const float* __restrict__ W_hh)
{
    const int bid = blockIdx.x;
    const int tid = threadIdx.x;

    if (bid < 512) {
        if (tid < 128)
            ((unsigned long long*)g_himg[0])[(size_t)bid * 128 + tid] = 0ull;
        if (bid == 0 && tid >= 128 && tid < 192)
            ((unsigned int*)g_hflag)[tid - 128] = 0u;

        const int t = bid >> 2, mg = bid & 3;
        const int cr = tid >> 2, s4 = tid & 3;
        const int b = mg * 64 + cr;
        const uint32_t seg = (s4 >> 1) * 2048 + cr * 32 + (((s4) ^ (cr >> 2)) & 1) * 16;
        unsigned char* base = g_ximg + (size_t)(t * 4 + mg) * 4 * 8192;
#pragma unroll
        for (int c = 0; c < 4; c++) {
            const float* src = x + (size_t)b * (Ssz * Fsz) + (size_t)t * Fsz + c * 32 + s4 * 8;
            float4 v0 = *(const float4*)src;
            float4 v1 = *(const float4*)(src + 4);
            unsigned short h[8], l[8];
            hsplit(v0.x, h[0], l[0]); hsplit(v0.y, h[1], l[1]);
            hsplit(v0.z, h[2], l[2]); hsplit(v0.w, h[3], l[3]);
            hsplit(v1.x, h[4], l[4]); hsplit(v1.y, h[5], l[5]);
            hsplit(v1.z, h[6], l[6]); hsplit(v1.w, h[7], l[7]);
            uint4 hp, lp;
            hp.x = (uint32_t)h[0] | ((uint32_t)h[1] << 16);
            hp.y = (uint32_t)h[2] | ((uint32_t)h[3] << 16);
            hp.z = (uint32_t)h[4] | ((uint32_t)h[5] << 16);
            hp.w = (uint32_t)h[6] | ((uint32_t)h[7] << 16);
            lp.x = (uint32_t)l[0] | ((uint32_t)l[1] << 16);
            lp.y = (uint32_t)l[2] | ((uint32_t)l[3] << 16);
            lp.z = (uint32_t)l[4] | ((uint32_t)l[5] << 16);
            lp.w = (uint32_t)l[6] | ((uint32_t)l[7] << 16);
            *(uint4*)(base + c * 8192 + seg)        = hp;
            *(uint4*)(base + c * 8192 + 4096 + seg) = lp;
        }
        return;
    }

    if (bid < 1152) {
        const int w = bid - 512;
        const int ns = w & 31, c = w >> 5;
        const int jl = tid & 15;
        const int g = (tid >> 4) & 3;
        const int kseg = tid >> 6;
        const int r = jl * 4 + g;
        const int col = g * Hsz + ns * 16 + jl;
        const int k0 = c * 32 + kseg * 8;
        unsigned short h[8];
#pragma unroll
        for (int e = 0; e < 8; e++) {
            const int k = k0 + e;
            float wv = (k < Fsz) ? W_ih[k * G4H + col] : W_hh[(k - Fsz) * G4H + col];
            __half hh = __float2half(wv);
            h[e] = *(unsigned short*)&hh;
        }
        uint4 hp;
        hp.x = (uint32_t)h[0] | ((uint32_t)h[1] << 16);
        hp.y = (uint32_t)h[2] | ((uint32_t)h[3] << 16);
        hp.z = (uint32_t)h[4] | ((uint32_t)h[5] << 16);
        hp.w = (uint32_t)h[6] | ((uint32_t)h[7] << 16);
        const uint32_t seg = (kseg >> 1) * 2048 + r * 32 + (((kseg ^ (r >> 2)) & 1) << 4);
        *(uint4*)(g_wimg + (size_t)ns * 81920 + (size_t)c * 4096 + seg) = hp;
        return;
    }

    // ---- ctx layer 1 ----
    {
        const int q = bid - 1152;
        const int n0 = (q & 7) * 64;
        const int m0 = (q >> 3) * 64;
        const int tc = tid & 15;
        const int rg = tid >> 4;

        __shared__ float As[16][68];
        __shared__ float Ws[16][68];

        float4 acc[4];
#pragma unroll
        for (int i = 0; i < 4; i++) acc[i] = make_float4(0.f, 0.f, 0.f, 0.f);

        for (int k0 = 0; k0 < 64; k0 += 16) {
#pragma unroll
            for (int u = 0; u < 4; u++) {
                int i = tid + u * 256;
                int r = i >> 4, kk = i & 15;
                As[kk][r] = context[(m0 + r) * 64 + k0 + kk];
                int kr = i >> 6, cc = i & 63;
                Ws[kr][cc] = cg_w1[(k0 + kr) * 512 + n0 + cc];
            }
            __syncthreads();
#pragma unroll
            for (int kk = 0; kk < 16; kk++) {
                float4 w = *(const float4*)&Ws[kk][tc * 4];
                float4 a = *(const float4*)&As[kk][rg * 4];
                acc[0].x += a.x * w.x; acc[0].y += a.x * w.y; acc[0].z += a.x * w.z; acc[0].w += a.x * w.w;
                acc[1].x += a.y * w.x; acc[1].y += a.y * w.y; acc[1].z += a.y * w.z; acc[1].w += a.y * w.w;
                acc[2].x += a.z * w.x; acc[2].y += a.z * w.y; acc[2].z += a.z * w.z; acc[2].w += a.z * w.w;
                acc[3].x += a.w * w.x; acc[3].y += a.w * w.y; acc[3].z += a.w * w.z; acc[3].w += a.w * w.w;
            }
            __syncthreads();
        }

        int col = n0 + tc * 4;
        float4 bv = *(const float4*)&cg_b1[col];
#pragma unroll
        for (int ri = 0; ri < 4; ri++) {
            int row = m0 + rg * 4 + ri;
            float4 v = acc[ri];
            v.x = fmaxf(v.x + bv.x, 0.f); v.y = fmaxf(v.y + bv.y, 0.f);
            v.z = fmaxf(v.z + bv.z, 0.f); v.w = fmaxf(v.w + bv.w, 0.f);
            *(float4*)&g_t1[row * 512 + col] = v;
        }
    }
}

// ---------------- ctx layer 2 ----------------
__global__ __launch_bounds__(256) void ctx2_kernel(
    const float* __restrict__ W, const float* __restrict__ bias)
{
    const int n0 = blockIdx.x * 64;
    const int m0 = blockIdx.y * 64;
    const int tid = threadIdx.x;
    const int tc = tid & 15;
    const int rg = tid >> 4;

    __shared__ float As[16][68];
    __shared__ float Ws[16][68];

    float4 acc[4];
#pragma unroll
    for (int i = 0; i < 4; i++) acc[i] = make_float4(0.f, 0.f, 0.f, 0.f);

    for (int k0 = 0; k0 < 512; k0 += 16) {
#pragma unroll
        for (int u = 0; u < 4; u++) {
            int i = tid + u * 256;
            int r = i >> 4, kk = i & 15;
            As[kk][r] = g_t1[(m0 + r) * 512 + k0 + kk];
            int kr = i >> 6, c = i & 63;
            Ws[kr][c] = W[(k0 + kr) * 1536 + n0 + c];
        }
        __syncthreads();
#pragma unroll
        for (int kk = 0; kk < 16; kk++) {
            float4 w = *(const float4*)&Ws[kk][tc * 4];
            float4 a = *(const float4*)&As[kk][rg * 4];
            acc[0].x += a.x * w.x; acc[0].y += a.x * w.y; acc[0].z += a.x * w.z; acc[0].w += a.x * w.w;
            acc[1].x += a.y * w.x; acc[1].y += a.y * w.y; acc[1].z += a.y * w.z; acc[1].w += a.y * w.w;
            acc[2].x += a.z * w.x; acc[2].y += a.z * w.y; acc[2].z += a.z * w.z; acc[2].w += a.z * w.w;
            acc[3].x += a.w * w.x; acc[3].y += a.w * w.y; acc[3].z += a.w * w.z; acc[3].w += a.w * w.w;
        }
        __syncthreads();
    }

    int col = n0 + tc * 4;
    float4 bv = *(const float4*)&bias[col];
#pragma unroll
    for (int ri = 0; ri < 4; ri++) {
        int row = m0 + rg * 4 + ri;
        float4 v = acc[ri];
        v.x = sigmoidf_(v.x + bv.x); v.y = sigmoidf_(v.y + bv.y);
        v.z = sigmoidf_(v.z + bv.z); v.w = sigmoidf_(v.w + bv.w);
        *(float4*)&g_ctx[row * 1536 + col] = v;
    }
}

// ---------------- persistent LSTM: fp16 2-pass, one producer WARP per stage ----------------
// 384 threads = 12 warps: warps 0-7 consume (MMA + epilogue),
// warps 8-11 produce: warp 8+s (lane 0) owns pipeline stage s.
__global__ __launch_bounds__(384, 1) void lstm_persist(
    const float* __restrict__ b_ih, const float* __restrict__ b_hh)
{
    extern __shared__ char smbuf[];
    const uint32_t sb = smem_to_u32(smbuf);
    const int tid = threadIdx.x;
    const int lane = tid & 31, wid = tid >> 5;
    const int bx = blockIdx.x;
    const int nsl = bx & 31;
    const int j0 = nsl * 16;
    const int mg = bx >> 5;
    const int m0 = mg * 64;

    const uint32_t mbF = sb + MB_OFF;
    const uint32_t mbE = sb + MB_OFF + 32;
    const uint32_t mbW = sb + MB_OFF + 64;

    if (tid == 0) {
#pragma unroll
        for (int s = 0; s < NSTG; s++) {
            MBARRIER_INIT(mbF + s * 8, 1);
            MBARRIER_INIT(mbE + s * 8, 8);
        }
        MBARRIER_INIT(mbW, 1);
    }
    FENCE_ASYNC_SHARED();
    __syncthreads();

    // ---- resident W slice (80KB fp16) ----
    if (tid == 0) {
        MBARRIER_EXPECT_TX(mbW, 81920u);
        const unsigned char* src = g_wimg + (size_t)nsl * 81920;
#pragma unroll
        for (int i = 0; i < 5; i++)
            bulk_g2s(sb + W_OFF + i * 16384, src + i * 16384, 16384u, mbW);
    }
    MBARRIER_WAIT_PARITY(mbW, 0);
    __syncthreads();

    if (wid >= 8) {
        // ======== producers: warp 8+s owns stage s (lane 0 active) ========
        if (lane == 0) {
            const int s = wid - 8;
            unsigned ph = 1u;        // empty barrier: first wait passes immediately
#pragma unroll 1
            for (int gc = s; gc < Ssz * CPS; gc += 4) {
                MBARRIER_WAIT_PARITY(mbE + s * 8, ph);
                ph ^= 1u;
                const int tp = gc / CPS, cc = gc % CPS;
                const unsigned char* src;
                if (cc < 2) {
                    src = g_ximg + ((size_t)(tp * 4 + mg) * 4 + 2 * cc) * 8192;
                } else {
                    if (tp > 0) {
                        const unsigned tgt = 16u * (unsigned)tp;
                        const int hc = 2 * cc - 4;
#pragma unroll
                        for (int q = 0; q < 2; q++) {
                            unsigned v;
                            do {
                                asm volatile("ld.global.acquire.gpu.u32 %0, [%1];"
                                             : "=r"(v) : "l"(&g_hflag[mg][hc + q]));
                                if (v >= tgt) break;
                                __nanosleep(32);
                            } while (true);
                        }
                    }
                    src = g_himg[tp & 1] + (size_t)(mg * 16 + (2 * cc - 4)) * 8192;
                }
                MBARRIER_EXPECT_TX(mbF + s * 8, 16384u);
                bulk_g2s(sb + ABASE + s * 16384,        src,        8192u, mbF + s * 8);
                bulk_g2s(sb + ABASE + s * 16384 + 8192, src + 8192, 8192u, mbF + s * 8);
            }
        }
        return;
    }

    // ================= consumers (warps 0-7) =================
    const int m0w = (wid >> 1) * 16;
    const int n0w = (wid & 1) * 32;
    const int rA = m0w + (lane & 15);
    const uint32_t offA = rA * 32 + ((((lane >> 4) ^ (rA >> 2)) & 1) << 4);
    const int rB = n0w + ((lane >> 4) << 3) + (lane & 7);
    const uint32_t offB = rB * 32 + ((((lane >> 3) ^ (rB >> 2)) & 1) << 4);

    const int rowc = m0w + (lane >> 2) + (lane & 1) * 8;
    const int bglob = m0 + rowc;
    int jc[4];
    float bi[4], bf4[4], bg4[4], bo4[4];
    float creg[4], cti[4], ctf[4], cto[4];
    uint32_t hoff[4];
#pragma unroll
    for (int nt = 0; nt < 4; nt++) {
        const int j = j0 + (n0w >> 2) + nt * 2 + ((lane >> 1) & 1);
        jc[nt] = j;
        bi[nt]  = b_ih[j]        + b_hh[j];
        bf4[nt] = b_ih[j + 512]  + b_hh[j + 512];
        bg4[nt] = b_ih[j + 1024] + b_hh[j + 1024];
        bo4[nt] = b_ih[j + 1536] + b_hh[j + 1536];
        cti[nt] = g_ctx[(size_t)bglob * (3 * Hsz) + j];
        ctf[nt] = g_ctx[(size_t)bglob * (3 * Hsz) + j + 512];
        cto[nt] = g_ctx[(size_t)bglob * (3 * Hsz) + j + 1024];
        creg[nt] = 0.f;
        const int hc = j >> 5, kj = j & 31, s4h = kj >> 3, eh = kj & 7;
        hoff[nt] = (uint32_t)(mg * 16 + hc) * 8192 + (s4h >> 1) * 2048 + (eh << 1)
                 + (uint32_t)rowc * 32
                 + ((((unsigned)s4h ^ ((unsigned)rowc >> 2)) & 1u) << 4);
    }

    unsigned fph = 0;

#pragma unroll 1
    for (int t = 0; t < Ssz; t++) {
        float acc[4][4];
#pragma unroll
        for (int i = 0; i < 4; i++)
#pragma unroll
            for (int q = 0; q < 4; q++) acc[i][q] = 0.f;

#pragma unroll 1
        for (int c = 0; c < CPS; c++) {
            const int gc = t * CPS + c;
            const int s = gc & 3;
            MBARRIER_WAIT_PARITY(mbF + s * 8, (fph >> s) & 1u);
            fph ^= (1u << s);

            const uint32_t st = sb + ABASE + s * 16384;
#pragma unroll
            for (int sub = 0; sub < 2; sub++) {
                const int oc = 2 * c + sub;
                const uint32_t ast = st + sub * 8192;
                const uint32_t wst = sb + W_OFF + oc * 4096;
#pragma unroll
                for (int kb = 0; kb < 2; kb++) {
                    uint32_t a0, a1, a2, a3, l0, l1, l2, l3;
                    LDSM4(a0, a1, a2, a3, ast + kb * 2048 + offA);
                    LDSM4(l0, l1, l2, l3, ast + 4096 + kb * 2048 + offA);
                    uint32_t b0, b1, b2, b3, b4, b5, b6, b7;
                    LDSM4(b0, b1, b2, b3, wst + kb * 2048 + offB);
                    LDSM4(b4, b5, b6, b7, wst + kb * 2048 + offB + 512);

                    MMAH(acc[0], a0, a1, a2, a3, b0, b1);
                    MMAH(acc[1], a0, a1, a2, a3, b2, b3);
                    MMAH(acc[2], a0, a1, a2, a3, b4, b5);
                    MMAH(acc[3], a0, a1, a2, a3, b6, b7);
                    MMAH(acc[0], l0, l1, l2, l3, b0, b1);
                    MMAH(acc[1], l0, l1, l2, l3, b2, b3);
                    MMAH(acc[2], l0, l1, l2, l3, b4, b5);
                    MMAH(acc[3], l0, l1, l2, l3, b6, b7);
                }
            }
            if (lane == 0) MBARRIER_ARRIVE(mbE + s * 8);
        }

        // ---- shuffle epilogue ----
        unsigned char* himg = g_himg[(t + 1) & 1];
        const bool oddq = (lane & 1);
#pragma unroll
        for (int nt = 0; nt < 4; nt++) {
            float x0 = __shfl_xor_sync(0xffffffffu, acc[nt][0], 1);
            float x1 = __shfl_xor_sync(0xffffffffu, acc[nt][1], 1);
            float x2 = __shfl_xor_sync(0xffffffffu, acc[nt][2], 1);
            float x3 = __shfl_xor_sync(0xffffffffu, acc[nt][3], 1);
            float g0, g1, g2, g3;
            if (!oddq) { g0 = acc[nt][0]; g1 = acc[nt][1]; g2 = x0; g3 = x1; }
            else       { g0 = x2; g1 = x3; g2 = acc[nt][2]; g3 = acc[nt][3]; }
            float iv = sigmoidf_(g0 + bi[nt])  * cti[nt];
            float fv = sigmoidf_(g1 + bf4[nt]) * ctf[nt];
            float gg = tanhf_(g2 + bg4[nt]);
            float ov = sigmoidf_(g3 + bo4[nt]) * cto[nt];
            float cn = fv * creg[nt] + iv * gg;
            creg[nt] = cn;
            float hn = ov * tanhf_(cn);
            __half hb = __float2half(hn);
            *(__half*)(himg + hoff[nt])        = hb;
            *(__half*)(himg + hoff[nt] + 4096) = __float2half(hn - __half2float(hb));
            if (t == Ssz - 1) g_h[bglob * Hsz + jc[nt]] = hn;
        }

        __syncwarp();
        if (lane == 0) {
            __threadfence();
            atomicAdd(&g_hflag[mg][nsl >> 1], 1u);
        }
    }
}

// ---------------- fused mu / log_var / z / decoder (one block per batch row) ----------------
__global__ __launch_bounds__(512) void mulvdec_kernel(
    const float* __restrict__ mu_w, const float* __restrict__ mu_b,
    const float* __restrict__ lv_w, const float* __restrict__ lv_b,
    const float* __restrict__ eps,
    const float* __restrict__ dec_w1, const float* __restrict__ dec_b1,
    const float* __restrict__ dec_w2, const float* __restrict__ dec_b2,
    float* __restrict__ out)
{
    const int b = blockIdx.x;
    const int tid = threadIdx.x;
    __shared__ float sh[512];
    __shared__ float smu[16], slv[16];
    __shared__ float sz[16];
    __shared__ float st[512];

    sh[tid] = g_h[b * Hsz + tid];
    __syncthreads();

    const int w = tid >> 5, lane = tid & 31;
    const int l = w;
    float sm = 0.f, sl = 0.f;
    for (int k = lane; k < Hsz; k += 32) {
        float hv = sh[k];
        sm += hv * mu_w[k * Lsz + l];
        sl += hv * lv_w[k * Lsz + l];
    }
#pragma unroll
    for (int o = 16; o > 0; o >>= 1) {
        sm += __shfl_down_sync(0xffffffffu, sm, o);
        sl += __shfl_down_sync(0xffffffffu, sl, o);
    }
    if (lane == 0) { smu[l] = sm; slv[l] = sl; }
    __syncthreads();

    if (tid < Lsz) {
        float mu = smu[tid] + mu_b[tid];
        float lv = slv[tid] + lv_b[tid];
        out[Bsz * Fsz + b * Lsz + tid] = mu;
        out[Bsz * Fsz + Bsz * Lsz + b * Lsz + tid] = lv;
        sz[tid] = mu + eps[b * Lsz + tid] * expf(0.5f * lv);
    }
    __syncthreads();

    // decoder layer 1
    {
        float s = dec_b1[tid];
#pragma unroll
        for (int k = 0; k < 16; k++) s += sz[k] * dec_w1[k * Hsz + tid];
        st[tid] = fmaxf(s, 0.f);
    }
    __syncthreads();

    // decoder layer 2 with 4 independent accumulators
    {
        const int col = tid & 127, qr = tid >> 7;
        const int kb = qr * 128;
        float r0 = 0.f, r1 = 0.f, r2 = 0.f, r3 = 0.f;
#pragma unroll 8
        for (int k = 0; k < 128; k += 4) {
            r0 += st[kb + k]     * dec_w2[(kb + k) * Fsz + col];
            r1 += st[kb + k + 1] * dec_w2[(kb + k + 1) * Fsz + col];
            r2 += st[kb + k + 2] * dec_w2[(kb + k + 2) * Fsz + col];
            r3 += st[kb + k + 3] * dec_w2[(kb + k + 3) * Fsz + col];
        }
        __shared__ float part[4][128];
        part[qr][col] = (r0 + r1) + (r2 + r3);
        __syncthreads();
        if (tid < 128) {
            out[b * Fsz + tid] = dec_b2[tid] +
                part[0][tid] + part[1][tid] + part[2][tid] + part[3][tid];
        }
    }
}

// ---------------- launch ----------------
extern "C" void kernel_launch(void* const* d_in, const int* in_sizes, int n_in,
                              void* d_out, int out_size)
{
    const float* x       = (const float*)d_in[0];
    const float* context = (const float*)d_in[1];
    const float* eps     = (const float*)d_in[2];
    const float* W_ih    = (const float*)d_in[3];
    const float* b_ih    = (const float*)d_in[4];
    const float* W_hh    = (const float*)d_in[5];
    const float* b_hh    = (const float*)d_in[6];
    const float* cg_w1   = (const float*)d_in[7];
    const float* cg_b1   = (const float*)d_in[8];
    const float* cg_w2   = (const float*)d_in[9];
    const float* cg_b2   = (const float*)d_in[10];
    const float* mu_w    = (const float*)d_in[11];
    const float* mu_b    = (const float*)d_in[12];
    const float* lv_w    = (const float*)d_in[13];
    const float* lv_b    = (const float*)d_in[14];
    const float* dec_w1  = (const float*)d_in[15];
    const float* dec_b1  = (const float*)d_in[16];
    const float* dec_w2  = (const float*)d_in[17];
    const float* dec_b2  = (const float*)d_in[18];
    float* out = (float*)d_out;

    static int smem_set = 0;
    if (!smem_set) {
        cudaFuncSetAttribute(lstm_persist, cudaFuncAttributeMaxDynamicSharedMemorySize,
                             SMEM_PERSIST);
        smem_set = 1;
    }

    prep_kernel<<<1184, 256>>>(x, context, cg_w1, cg_b1, W_ih, W_hh);
    ctx2_kernel<<<dim3(24, 4), 256>>>(cg_w2, cg_b2);

    lstm_persist<<<128, 384, SMEM_PERSIST>>>(b_ih, b_hh);

    mulvdec_kernel<<<Bsz, 512>>>(mu_w, mu_b, lv_w, lv_b, eps,
                                 dec_w1, dec_b1, dec_w2, dec_b2, out);
}